// round 4
// baseline (speedup 1.0000x reference)
#include <cuda_runtime.h>
#include <cstdint>
#include <cstddef>
#include <math.h>

// ---------------------------------------------------------------------------
// MoE layer: x[2,2048,1024] f32, router Wr[1024,8], experts W1[8,1024,4096],
// b1[8,4096], W2[8,4096,1024], b2[8,1024]. top-2 routing, exact GELU.
// Pipeline (all graph-capturable, no atomics on the output):
//   init -> router(top2 + counts) -> scan(padded offsets) -> scatter(slots)
//   -> grouped GEMM1 (gather x, tf32 mma, +b1, gelu) -> H scratch
//   -> grouped GEMM2 (H @ W2 + b2) -> Y scratch
//   -> combine: out[t] = w0*Y[s0] + w1*Y[s1]
// GEMMs: 128x128x32 tiles, tf32 mma.sync, 3-stage cp.async pipeline in
// dynamic smem, one __syncthreads per k-iter.
// ---------------------------------------------------------------------------

constexpr int HID_ = 1024;
constexpr int FFN_ = 4096;
constexpr int NE_  = 8;
constexpr int T_   = 4096;          // tokens = 2*2048

constexpr int BM = 128, BN = 128, BK = 32;
constexpr int STAGES = 3;
constexpr int ASTRIDE = 36;         // floats per A row in smem (32 + 4 pad, conflict-free)
constexpr int BSTRIDE = 136;        // floats per B row in smem (128 + 8, conflict-free)
constexpr int MAX_SLOTS = T_ * 2 + NE_ * BM;   // 9216 (worst-case padded)
constexpr int ROW_TILES = MAX_SLOTS / BM;      // 72

constexpr uint32_t ABUF = sizeof(float) * BM * ASTRIDE;   // bytes per A stage (18432)
constexpr uint32_t BBUF = sizeof(float) * BK * BSTRIDE;   // bytes per B stage (17408)
constexpr int SMEM_BYTES = STAGES * (int)(ABUF + BBUF);   // 107520

// ---------------- scratch (__device__ globals: allocation-guard safe) ------
__device__ float g_H[(size_t)MAX_SLOTS * FFN_];   // expert-1 activations
__device__ float g_Y[(size_t)MAX_SLOTS * HID_];   // expert-2 outputs per slot
__device__ int   g_slot_tok[MAX_SLOTS];           // slot -> token (-1 = pad)
__device__ int   g_tok_slot[T_ * 2];              // (token,k) -> slot
__device__ int   g_top_i[T_ * 2];
__device__ float g_top_w[T_ * 2];
__device__ int   g_counts[NE_];
__device__ int   g_fill[NE_];
__device__ int   g_poff[NE_ + 1];                 // padded expert offsets

// ---------------- small helpers --------------------------------------------
__device__ __forceinline__ uint32_t f2tf32(float f) {
    uint32_t r;
    asm("cvt.rna.tf32.f32 %0, %1;" : "=r"(r) : "f"(f));
    return r;
}

__device__ __forceinline__ void mma_tf32(float* c, const uint32_t* a, const uint32_t* b) {
    asm volatile(
        "mma.sync.aligned.m16n8k8.row.col.f32.tf32.tf32.f32 "
        "{%0,%1,%2,%3}, {%4,%5,%6,%7}, {%8,%9}, {%0,%1,%2,%3};"
        : "+f"(c[0]), "+f"(c[1]), "+f"(c[2]), "+f"(c[3])
        : "r"(a[0]), "r"(a[1]), "r"(a[2]), "r"(a[3]),
          "r"(b[0]), "r"(b[1]));
}

__device__ __forceinline__ void cp16(uint32_t smem_addr, const void* gptr, int src_bytes) {
    asm volatile("cp.async.cg.shared.global [%0], [%1], 16, %2;"
                 :: "r"(smem_addr), "l"(gptr), "r"(src_bytes) : "memory");
}

__device__ __forceinline__ float gelu_exact(float v) {
    return 0.5f * v * (1.0f + erff(v * 0.70710678118654752440f));
}

// ---------------- init ------------------------------------------------------
__global__ void init_kernel() {
    int i = blockIdx.x * blockDim.x + threadIdx.x;
    if (i < MAX_SLOTS) g_slot_tok[i] = -1;
    if (i < NE_) { g_counts[i] = 0; g_fill[i] = 0; }
}

// ---------------- router: one warp per token --------------------------------
__global__ void router_kernel(const float* __restrict__ x, const float* __restrict__ Wr) {
    int gw = (blockIdx.x * blockDim.x + threadIdx.x) >> 5;
    int lane = threadIdx.x & 31;
    if (gw >= T_) return;
    const float* xr = x + (size_t)gw * HID_;
    float acc[NE_];
#pragma unroll
    for (int e = 0; e < NE_; e++) acc[e] = 0.f;
    for (int j = lane; j < HID_; j += 32) {
        float xv = xr[j];
        const float4* w4 = (const float4*)(Wr + (size_t)j * NE_);
        float4 a = w4[0], b = w4[1];
        acc[0] += xv * a.x; acc[1] += xv * a.y; acc[2] += xv * a.z; acc[3] += xv * a.w;
        acc[4] += xv * b.x; acc[5] += xv * b.y; acc[6] += xv * b.z; acc[7] += xv * b.w;
    }
#pragma unroll
    for (int off = 16; off > 0; off >>= 1)
#pragma unroll
        for (int e = 0; e < NE_; e++)
            acc[e] += __shfl_xor_sync(0xffffffffu, acc[e], off);
    if (lane == 0) {
        int i0 = 0;
#pragma unroll
        for (int e = 1; e < NE_; e++) if (acc[e] > acc[i0]) i0 = e;   // strict > : ties keep low idx (jax)
        int i1 = (i0 == 0) ? 1 : 0;
#pragma unroll
        for (int e = 0; e < NE_; e++) if (e != i0 && acc[e] > acc[i1]) i1 = e;
        // renormalized top-2 softmax == softmax over {l0, l1}
        float d = acc[i1] - acc[i0];             // <= 0
        float w1v = 1.f / (1.f + expf(-d));      // sigmoid(l1 - l0)
        float w0v = 1.f - w1v;
        g_top_i[2 * gw] = i0;  g_top_i[2 * gw + 1] = i1;
        g_top_w[2 * gw] = w0v; g_top_w[2 * gw + 1] = w1v;
        atomicAdd(&g_counts[i0], 1);
        atomicAdd(&g_counts[i1], 1);
    }
}

// ---------------- scan: padded exclusive offsets ----------------------------
__global__ void scan_kernel() {
    if (threadIdx.x == 0) {
        int o = 0;
#pragma unroll
        for (int e = 0; e < NE_; e++) {
            g_poff[e] = o;
            o += ((g_counts[e] + BM - 1) / BM) * BM;
        }
        g_poff[NE_] = o;
    }
}

// ---------------- scatter: token -> slot ------------------------------------
__global__ void scatter_kernel() {
    int tk = blockIdx.x * blockDim.x + threadIdx.x;   // (token, k) pair index
    if (tk >= T_ * 2) return;
    int e = g_top_i[tk];
    int p = atomicAdd(&g_fill[e], 1);
    int s = g_poff[e] + p;
    g_slot_tok[s] = tk >> 1;
    g_tok_slot[tk] = s;
}

// ---------------- grouped GEMM (tf32 mma.sync, 3-stage cp.async, BK=32) -----
// FFN1=true : A = gathered x rows (KD=1024), B = W1[e], out = gelu(A@B + b1) -> g_H
// FFN1=false: A = g_H rows (KD=4096),       B = W2[e], out = A@B + b2        -> g_Y
template <int KD, int ND, bool FFN1>
__global__ void __launch_bounds__(256, 2)
moe_gemm_kernel(const float* __restrict__ Asrc,
                const float* __restrict__ W,
                const float* __restrict__ bias) {
    extern __shared__ float smem_dyn[];
    // layout: STAGES A tiles, then STAGES B tiles
    float* As_base = smem_dyn;                               // [STAGES][BM][ASTRIDE]
    float* Bs_base = smem_dyn + STAGES * BM * ASTRIDE;       // [STAGES][BK][BSTRIDE]

    const int row0 = blockIdx.x * BM;
    if (row0 >= g_poff[NE_]) return;
    int e = 0;
#pragma unroll
    for (int i = 1; i < NE_; i++) if (g_poff[i] <= row0) e = i;

    const float* Ap = FFN1 ? Asrc : g_H;
    float*       Op = FFN1 ? g_H : g_Y;
    const float* Wb = W + (size_t)e * KD * ND;
    const int n0 = blockIdx.y * BN;
    const int tid = threadIdx.x;

    // per-thread global->smem assignments (4 A quads, 4 B quads per stage)
    const float* agp[4]; uint32_t asmem[4]; int apred[4];
#pragma unroll
    for (int it = 0; it < 4; it++) {
        int q = tid + it * 256;        // quad index within 1024-quad A stage
        int r = q >> 3, c4 = q & 7;    // 8 quads (32 floats) per row
        int s = row0 + r;
        int pred = 16;
        const float* gp;
        if (FFN1) {
            int tok = g_slot_tok[s];
            if (tok < 0) { pred = 0; tok = 0; }   // pad row -> cp.async zero-fill
            gp = Ap + (size_t)tok * KD;
        } else {
            gp = Ap + (size_t)s * KD;
        }
        agp[it] = gp + c4 * 4;
        apred[it] = pred;
        asmem[it] = (uint32_t)__cvta_generic_to_shared(&As_base[r * ASTRIDE + c4 * 4]);
    }
    const float* bgp[4]; uint32_t bsmem[4];
#pragma unroll
    for (int it = 0; it < 4; it++) {
        int q = tid + it * 256;        // quad index within 1024-quad B stage
        int k = q >> 5, nq = q & 31;   // 32 quads (128 floats) per k-row
        bgp[it] = Wb + (size_t)k * ND + n0 + nq * 4;
        bsmem[it] = (uint32_t)__cvta_generic_to_shared(&Bs_base[k * BSTRIDE + nq * 4]);
    }

    const int lane = tid & 31, warp = tid >> 5;
    const int wm = warp >> 1, wn = warp & 1;   // 4 x 2 warp grid; 32x64 per warp
    const int gg = lane >> 2, tt = lane & 3;

    float acc[2][8][4];
#pragma unroll
    for (int a = 0; a < 2; a++)
#pragma unroll
        for (int b = 0; b < 8; b++)
#pragma unroll
            for (int c = 0; c < 4; c++) acc[a][b][c] = 0.f;

    const int KT = KD / BK;            // 32 (GEMM1) or 128 (GEMM2)

    // prefetch stages 0 and 1
#pragma unroll
    for (int s = 0; s < STAGES - 1; s++) {
#pragma unroll
        for (int it = 0; it < 4; it++)
            cp16(asmem[it] + s * ABUF, agp[it] + (size_t)s * BK, apred[it]);
#pragma unroll
        for (int it = 0; it < 4; it++)
            cp16(bsmem[it] + s * BBUF, bgp[it] + (size_t)s * BK * ND, 16);
        asm volatile("cp.async.commit_group;" ::: "memory");
    }

    for (int kt = 0; kt < KT; ++kt) {
        // ensure stage kt has landed (stage kt+1 may remain in flight)
        if (kt + 1 < KT) asm volatile("cp.async.wait_group %0;" :: "n"(STAGES - 2) : "memory");
        else             asm volatile("cp.async.wait_group 0;" ::: "memory");
        __syncthreads();   // single barrier per k-iter: also makes buf (kt+2)%3 reusable

        // issue stage kt+2 before compute so copies overlap this iter's mma
        if (kt + STAGES - 1 < KT) {
            const int sb = (kt + STAGES - 1) % STAGES;
            const uint32_t ao = sb * ABUF, bo = sb * BBUF;
#pragma unroll
            for (int it = 0; it < 4; it++)
                cp16(asmem[it] + ao, agp[it] + (size_t)(kt + STAGES - 1) * BK, apred[it]);
#pragma unroll
            for (int it = 0; it < 4; it++)
                cp16(bsmem[it] + bo, bgp[it] + (size_t)(kt + STAGES - 1) * BK * ND, 16);
            asm volatile("cp.async.commit_group;" ::: "memory");
        }

        const int buf = kt % STAGES;
        const float* Asb = As_base + buf * BM * ASTRIDE;
        const float* Bsb = Bs_base + buf * BK * BSTRIDE;
#pragma unroll
        for (int kk = 0; kk < BK; kk += 8) {
            uint32_t af[2][4], bf[8][2];
#pragma unroll
            for (int mi = 0; mi < 2; mi++) {
                int r = wm * 32 + mi * 16 + gg;
                af[mi][0] = f2tf32(Asb[r * ASTRIDE + kk + tt]);
                af[mi][1] = f2tf32(Asb[(r + 8) * ASTRIDE + kk + tt]);
                af[mi][2] = f2tf32(Asb[r * ASTRIDE + kk + tt + 4]);
                af[mi][3] = f2tf32(Asb[(r + 8) * ASTRIDE + kk + tt + 4]);
            }
#pragma unroll
            for (int ni = 0; ni < 8; ni++) {
                int n = wn * 64 + ni * 8 + gg;
                bf[ni][0] = f2tf32(Bsb[(kk + tt) * BSTRIDE + n]);
                bf[ni][1] = f2tf32(Bsb[(kk + tt + 4) * BSTRIDE + n]);
            }
#pragma unroll
            for (int mi = 0; mi < 2; mi++)
#pragma unroll
                for (int ni = 0; ni < 8; ni++)
                    mma_tf32(acc[mi][ni], af[mi], bf[ni]);
        }
    }

    // epilogue: c0/c1 -> row gg, cols 2t/2t+1 ; c2/c3 -> row gg+8
#pragma unroll
    for (int mi = 0; mi < 2; mi++) {
#pragma unroll
        for (int half = 0; half < 2; half++) {
            int r = row0 + wm * 32 + mi * 16 + gg + half * 8;
#pragma unroll
            for (int ni = 0; ni < 8; ni++) {
                int col = n0 + wn * 64 + ni * 8 + 2 * tt;
                float v0 = acc[mi][ni][half * 2 + 0] + bias[(size_t)e * ND + col];
                float v1 = acc[mi][ni][half * 2 + 1] + bias[(size_t)e * ND + col + 1];
                if (FFN1) { v0 = gelu_exact(v0); v1 = gelu_exact(v1); }
                float2 v; v.x = v0; v.y = v1;
                *(float2*)&Op[(size_t)r * ND + col] = v;
            }
        }
    }
}

// ---------------- combine: out[t] = w0*Y[s0] + w1*Y[s1] ---------------------
__global__ void combine_kernel(float* __restrict__ out) {
    int i = blockIdx.x * blockDim.x + threadIdx.x;       // float4 index
    if (i >= T_ * HID_ / 4) return;
    int t = i / (HID_ / 4);
    int c4 = i % (HID_ / 4);
    int s0 = g_tok_slot[2 * t], s1 = g_tok_slot[2 * t + 1];
    float w0 = g_top_w[2 * t], w1 = g_top_w[2 * t + 1];
    float4 y0 = ((const float4*)(g_Y + (size_t)s0 * HID_))[c4];
    float4 y1 = ((const float4*)(g_Y + (size_t)s1 * HID_))[c4];
    float4 r;
    r.x = w0 * y0.x + w1 * y1.x;
    r.y = w0 * y0.y + w1 * y1.y;
    r.z = w0 * y0.z + w1 * y1.z;
    r.w = w0 * y0.w + w1 * y1.w;
    ((float4*)(out + (size_t)t * HID_))[c4] = r;
}

// ---------------- launch ----------------------------------------------------
extern "C" void kernel_launch(void* const* d_in, const int* in_sizes, int n_in,
                              void* d_out, int out_size) {
    (void)in_sizes; (void)n_in; (void)out_size;
    const float* x  = (const float*)d_in[0];
    const float* Wr = (const float*)d_in[1];
    const float* W1 = (const float*)d_in[2];
    const float* b1 = (const float*)d_in[3];
    const float* W2 = (const float*)d_in[4];
    const float* b2 = (const float*)d_in[5];
    float* out = (float*)d_out;

    // opt-in for >48KB dynamic smem (host-side attribute, legal during capture)
    cudaFuncSetAttribute(moe_gemm_kernel<HID_, FFN_, true>,
                         cudaFuncAttributeMaxDynamicSharedMemorySize, SMEM_BYTES);
    cudaFuncSetAttribute(moe_gemm_kernel<FFN_, HID_, false>,
                         cudaFuncAttributeMaxDynamicSharedMemorySize, SMEM_BYTES);

    init_kernel<<<(MAX_SLOTS + 255) / 256, 256>>>();
    router_kernel<<<(T_ * 32 + 255) / 256, 256>>>(x, Wr);
    scan_kernel<<<1, 32>>>();
    scatter_kernel<<<(T_ * 2 + 255) / 256, 256>>>();

    moe_gemm_kernel<HID_, FFN_, true>
        <<<dim3(ROW_TILES, FFN_ / BN), 256, SMEM_BYTES>>>(x, W1, b1);
    moe_gemm_kernel<FFN_, HID_, false>
        <<<dim3(ROW_TILES, HID_ / BN), 256, SMEM_BYTES>>>(x, W2, b2);

    combine_kernel<<<(T_ * HID_ / 4 + 255) / 256, 256>>>(out);
}

// round 8
// speedup vs baseline: 1.0453x; 1.0453x over previous
#include <cuda_runtime.h>
#include <cstdint>
#include <cstddef>
#include <math.h>

// ---------------------------------------------------------------------------
// MoE layer, legacy tensor path (sm_103-safe: mma.sync only, no tcgen05).
//   init -> router -> scan -> scatter -> cvt(x,W1,W2 -> tf32 bits)
//   -> GEMM1 (gather x, tf32 mma, +b1, gelu) -> g_H (tf32 bits)
//   -> GEMM2 (g_H @ W2 + b2)                 -> g_Y (f32)
//   -> combine
// GEMMs: 128x256x32 tiles, warp tile 64x64 (2x4 warp grid, 256 thr),
// 3-stage cp.async, zero CVT in mainloop (inputs pre-rounded to tf32).
// ---------------------------------------------------------------------------

constexpr int HID_ = 1024;
constexpr int FFN_ = 4096;
constexpr int NE_  = 8;
constexpr int T_   = 4096;

constexpr int BM = 128, BN = 256, BK = 32;
constexpr int STAGES = 3;
constexpr int ASTRIDE = 36;          // 32 + 4 pad: af banks (4g+t) all distinct
constexpr int BSTRIDE = 264;         // 256 + 8: bf banks (8t+g) all distinct
constexpr int MAX_SLOTS = T_ * 2 + NE_ * BM;   // 9216
constexpr int ROW_TILES = MAX_SLOTS / BM;      // 72

constexpr uint32_t ABUF = sizeof(float) * BM * ASTRIDE;   // 18432 B
constexpr uint32_t BBUF = sizeof(float) * BK * BSTRIDE;   // 33792 B
constexpr int SOFF_BIAS = STAGES * (int)(ABUF + BBUF);    // 156672
constexpr int SMEM_BYTES = SOFF_BIAS + BN * 4;            // 157696

// ---------------- scratch ---------------------------------------------------
__device__ float g_H[(size_t)MAX_SLOTS * FFN_];     // GEMM1 out (tf32 bits)
__device__ float g_Y[(size_t)MAX_SLOTS * HID_];     // GEMM2 out (f32)
__device__ float g_xc[(size_t)T_ * HID_];           // x  -> tf32 bits
__device__ float g_W1c[(size_t)NE_ * HID_ * FFN_];  // W1 -> tf32 bits
__device__ float g_W2c[(size_t)NE_ * FFN_ * HID_];  // W2 -> tf32 bits
__device__ int   g_slot_tok[MAX_SLOTS];
__device__ int   g_tok_slot[T_ * 2];
__device__ int   g_top_i[T_ * 2];
__device__ float g_top_w[T_ * 2];
__device__ int   g_counts[NE_];
__device__ int   g_fill[NE_];
__device__ int   g_poff[NE_ + 1];

// ---------------- helpers ---------------------------------------------------
__device__ __forceinline__ uint32_t f2tf32(float f) {
    uint32_t r;
    asm("cvt.rna.tf32.f32 %0, %1;" : "=r"(r) : "f"(f));
    return r;
}
__device__ __forceinline__ void mma_tf32(float* c, const uint32_t* a, const uint32_t* b) {
    asm volatile(
        "mma.sync.aligned.m16n8k8.row.col.f32.tf32.tf32.f32 "
        "{%0,%1,%2,%3}, {%4,%5,%6,%7}, {%8,%9}, {%0,%1,%2,%3};"
        : "+f"(c[0]), "+f"(c[1]), "+f"(c[2]), "+f"(c[3])
        : "r"(a[0]), "r"(a[1]), "r"(a[2]), "r"(a[3]),
          "r"(b[0]), "r"(b[1]));
}
__device__ __forceinline__ void cp16(uint32_t smem_addr, const void* gptr, int src_bytes) {
    asm volatile("cp.async.cg.shared.global [%0], [%1], 16, %2;"
                 :: "r"(smem_addr), "l"(gptr), "r"(src_bytes) : "memory");
}
__device__ __forceinline__ float gelu_exact(float v) {
    return 0.5f * v * (1.0f + erff(v * 0.70710678118654752440f));
}

// ---------------- init / router / scan / scatter ----------------------------
__global__ void init_kernel() {
    int i = blockIdx.x * blockDim.x + threadIdx.x;
    if (i < MAX_SLOTS) g_slot_tok[i] = -1;
    if (i < NE_) { g_counts[i] = 0; g_fill[i] = 0; }
}

__global__ void router_kernel(const float* __restrict__ x, const float* __restrict__ Wr) {
    int gw = (blockIdx.x * blockDim.x + threadIdx.x) >> 5;
    int lane = threadIdx.x & 31;
    if (gw >= T_) return;
    const float* xr = x + (size_t)gw * HID_;
    float acc[NE_];
#pragma unroll
    for (int e = 0; e < NE_; e++) acc[e] = 0.f;
    for (int j = lane; j < HID_; j += 32) {
        float xv = xr[j];
        const float4* w4 = (const float4*)(Wr + (size_t)j * NE_);
        float4 a = w4[0], b = w4[1];
        acc[0] += xv * a.x; acc[1] += xv * a.y; acc[2] += xv * a.z; acc[3] += xv * a.w;
        acc[4] += xv * b.x; acc[5] += xv * b.y; acc[6] += xv * b.z; acc[7] += xv * b.w;
    }
#pragma unroll
    for (int off = 16; off > 0; off >>= 1)
#pragma unroll
        for (int e = 0; e < NE_; e++)
            acc[e] += __shfl_xor_sync(0xffffffffu, acc[e], off);
    if (lane == 0) {
        int i0 = 0;
#pragma unroll
        for (int e = 1; e < NE_; e++) if (acc[e] > acc[i0]) i0 = e;
        int i1 = (i0 == 0) ? 1 : 0;
#pragma unroll
        for (int e = 0; e < NE_; e++) if (e != i0 && acc[e] > acc[i1]) i1 = e;
        float d = acc[i1] - acc[i0];
        float w1v = 1.f / (1.f + expf(-d));
        float w0v = 1.f - w1v;
        g_top_i[2 * gw] = i0;  g_top_i[2 * gw + 1] = i1;
        g_top_w[2 * gw] = w0v; g_top_w[2 * gw + 1] = w1v;
        atomicAdd(&g_counts[i0], 1);
        atomicAdd(&g_counts[i1], 1);
    }
}

__global__ void scan_kernel() {
    if (threadIdx.x == 0) {
        int o = 0;
#pragma unroll
        for (int e = 0; e < NE_; e++) {
            g_poff[e] = o;
            o += ((g_counts[e] + BM - 1) / BM) * BM;
        }
        g_poff[NE_] = o;
    }
}

__global__ void scatter_kernel() {
    int tk = blockIdx.x * blockDim.x + threadIdx.x;
    if (tk >= T_ * 2) return;
    int e = g_top_i[tk];
    int p = atomicAdd(&g_fill[e], 1);
    int s = g_poff[e] + p;
    g_slot_tok[s] = tk >> 1;
    g_tok_slot[tk] = s;
}

// ---------------- tf32 pre-convert (grid-stride) ----------------------------
__global__ void cvt_tf32_kernel(const float4* __restrict__ src, float4* __restrict__ dst, int n4) {
    for (int i = blockIdx.x * blockDim.x + threadIdx.x; i < n4; i += gridDim.x * blockDim.x) {
        float4 v = src[i];
        v.x = __uint_as_float(f2tf32(v.x));
        v.y = __uint_as_float(f2tf32(v.y));
        v.z = __uint_as_float(f2tf32(v.z));
        v.w = __uint_as_float(f2tf32(v.w));
        dst[i] = v;
    }
}

// ---------------- grouped GEMM (tf32 mma.sync, warp tile 64x64) -------------
// FFN1=true : A = gathered g_xc rows (KD=1024), B = g_W1c[e], out = tf32(gelu(A@B+b1)) -> g_H
// FFN1=false: A = g_H rows (KD=4096),           B = g_W2c[e], out = A@B+b2             -> g_Y
template <int KD, int ND, bool FFN1>
__global__ void __launch_bounds__(256, 1)
moe_gemm_kernel(const float* __restrict__ Asrc,
                const float* __restrict__ W,
                const float* __restrict__ bias) {
    extern __shared__ float smem_dyn[];
    float* As_base = smem_dyn;                               // [STAGES][BM][ASTRIDE]
    float* Bs_base = smem_dyn + STAGES * BM * ASTRIDE;       // [STAGES][BK][BSTRIDE]
    float* bias_s  = smem_dyn + SOFF_BIAS / 4;               // [BN]

    const int row0 = blockIdx.x * BM;
    if (row0 >= g_poff[NE_]) return;
    int e = 0;
#pragma unroll
    for (int i = 1; i < NE_; i++) if (g_poff[i] <= row0) e = i;

    const float* Ap = FFN1 ? Asrc : g_H;
    float*       Op = FFN1 ? g_H : g_Y;
    const float* Wb = W + (size_t)e * KD * ND;
    const int n0 = blockIdx.y * BN;
    const int tid = threadIdx.x;

    bias_s[tid] = bias[(size_t)e * ND + n0 + tid];   // 256 threads, BN=256

    // ---- per-thread cp.async assignments (stage-0 relative) ----
    // A: 128 rows x 8 quads = 1024 quads, 4 per thread
    const float* agp[4]; uint32_t asmem[4]; int apred[4];
#pragma unroll
    for (int it = 0; it < 4; it++) {
        int q = tid + it * 256;
        int r = q >> 3, c4 = q & 7;
        int s = row0 + r;
        int pred = 16;
        const float* gp;
        if (FFN1) {
            int tok = g_slot_tok[s];
            if (tok < 0) { pred = 0; tok = 0; }   // pad row -> cp.async zero-fill
            gp = Ap + (size_t)tok * KD;
        } else {
            gp = Ap + (size_t)s * KD;
        }
        agp[it] = gp + c4 * 4;
        apred[it] = pred;
        asmem[it] = (uint32_t)__cvta_generic_to_shared(&As_base[r * ASTRIDE + c4 * 4]);
    }
    // B: 32 k-rows x 64 quads = 2048 quads, 8 per thread
    const float* bgp[8]; uint32_t bsmem[8];
#pragma unroll
    for (int it = 0; it < 8; it++) {
        int q = tid + it * 256;
        int k = q >> 6, nq = q & 63;
        bgp[it] = Wb + (size_t)k * ND + n0 + nq * 4;
        bsmem[it] = (uint32_t)__cvta_generic_to_shared(&Bs_base[k * BSTRIDE + nq * 4]);
    }

    const int lane = tid & 31, warp = tid >> 5;
    const int wm = warp >> 2, wn = warp & 3;   // 2 x 4 warp grid; 64x64 per warp
    const int gg = lane >> 2, tt = lane & 3;

    float acc[4][8][4];
#pragma unroll
    for (int a = 0; a < 4; a++)
#pragma unroll
        for (int b = 0; b < 8; b++)
#pragma unroll
            for (int c = 0; c < 4; c++) acc[a][b][c] = 0.f;

    const int KT = KD / BK;   // 32 (GEMM1) or 128 (GEMM2)

    // prefetch stages 0,1
#pragma unroll
    for (int s = 0; s < STAGES - 1; s++) {
#pragma unroll
        for (int it = 0; it < 4; it++)
            cp16(asmem[it] + s * ABUF, agp[it] + (size_t)s * BK, apred[it]);
#pragma unroll
        for (int it = 0; it < 8; it++)
            cp16(bsmem[it] + s * BBUF, bgp[it] + (size_t)s * BK * ND, 16);
        asm volatile("cp.async.commit_group;" ::: "memory");
    }

    for (int kt = 0; kt < KT; ++kt) {
        if (kt + 1 < KT) asm volatile("cp.async.wait_group 1;" ::: "memory");
        else             asm volatile("cp.async.wait_group 0;" ::: "memory");
        __syncthreads();   // single barrier per k-iter; buf (kt+2)%3 reusable after it

        if (kt + 2 < KT) {
            const int sb = (kt + 2) % STAGES;
            const uint32_t ao = sb * ABUF, bo = sb * BBUF;
#pragma unroll
            for (int it = 0; it < 4; it++)
                cp16(asmem[it] + ao, agp[it] + (size_t)(kt + 2) * BK, apred[it]);
#pragma unroll
            for (int it = 0; it < 8; it++)
                cp16(bsmem[it] + bo, bgp[it] + (size_t)(kt + 2) * BK * ND, 16);
            asm volatile("cp.async.commit_group;" ::: "memory");
        }

        const int buf = kt % STAGES;
        const float* Asb = As_base + buf * BM * ASTRIDE;
        const float* Bsb = Bs_base + buf * BK * BSTRIDE;
#pragma unroll
        for (int kk = 0; kk < BK; kk += 8) {
            uint32_t af[4][4], bf[8][2];
#pragma unroll
            for (int mi = 0; mi < 4; mi++) {
                int r = wm * 64 + mi * 16 + gg;
                af[mi][0] = __float_as_uint(Asb[r * ASTRIDE + kk + tt]);
                af[mi][1] = __float_as_uint(Asb[(r + 8) * ASTRIDE + kk + tt]);
                af[mi][2] = __float_as_uint(Asb[r * ASTRIDE + kk + tt + 4]);
                af[mi][3] = __float_as_uint(Asb[(r + 8) * ASTRIDE + kk + tt + 4]);
            }
#pragma unroll
            for (int ni = 0; ni < 8; ni++) {
                int n = wn * 64 + ni * 8 + gg;
                bf[ni][0] = __float_as_uint(Bsb[(kk + tt) * BSTRIDE + n]);
                bf[ni][1] = __float_as_uint(Bsb[(kk + tt + 4) * BSTRIDE + n]);
            }
#pragma unroll
            for (int mi = 0; mi < 4; mi++)
#pragma unroll
                for (int ni = 0; ni < 8; ni++)
                    mma_tf32(acc[mi][ni], af[mi], bf[ni]);
        }
    }

    // epilogue
#pragma unroll
    for (int mi = 0; mi < 4; mi++) {
#pragma unroll
        for (int half = 0; half < 2; half++) {
            int r = row0 + wm * 64 + mi * 16 + gg + half * 8;
#pragma unroll
            for (int ni = 0; ni < 8; ni++) {
                int colL = wn * 64 + ni * 8 + 2 * tt;
                float v0 = acc[mi][ni][half * 2 + 0] + bias_s[colL];
                float v1 = acc[mi][ni][half * 2 + 1] + bias_s[colL + 1];
                if (FFN1) {
                    v0 = __uint_as_float(f2tf32(gelu_exact(v0)));
                    v1 = __uint_as_float(f2tf32(gelu_exact(v1)));
                }
                float2 v; v.x = v0; v.y = v1;
                *(float2*)&Op[(size_t)r * ND + n0 + colL] = v;
            }
        }
    }
}

// ---------------- combine ----------------------------------------------------
__global__ void combine_kernel(float* __restrict__ out) {
    int i = blockIdx.x * blockDim.x + threadIdx.x;
    if (i >= T_ * HID_ / 4) return;
    int t = i / (HID_ / 4);
    int c4 = i % (HID_ / 4);
    int s0 = g_tok_slot[2 * t], s1 = g_tok_slot[2 * t + 1];
    float w0 = g_top_w[2 * t], w1 = g_top_w[2 * t + 1];
    float4 y0 = ((const float4*)(g_Y + (size_t)s0 * HID_))[c4];
    float4 y1 = ((const float4*)(g_Y + (size_t)s1 * HID_))[c4];
    float4 r;
    r.x = w0 * y0.x + w1 * y1.x;
    r.y = w0 * y0.y + w1 * y1.y;
    r.z = w0 * y0.z + w1 * y1.z;
    r.w = w0 * y0.w + w1 * y1.w;
    ((float4*)(out + (size_t)t * HID_))[c4] = r;
}

// ---------------- launch ----------------------------------------------------
extern "C" void kernel_launch(void* const* d_in, const int* in_sizes, int n_in,
                              void* d_out, int out_size) {
    (void)in_sizes; (void)n_in; (void)out_size;
    const float* x  = (const float*)d_in[0];
    const float* Wr = (const float*)d_in[1];
    const float* W1 = (const float*)d_in[2];
    const float* b1 = (const float*)d_in[3];
    const float* W2 = (const float*)d_in[4];
    const float* b2 = (const float*)d_in[5];
    float* out = (float*)d_out;

    cudaFuncSetAttribute(moe_gemm_kernel<HID_, FFN_, true>,
                         cudaFuncAttributeMaxDynamicSharedMemorySize, SMEM_BYTES);
    cudaFuncSetAttribute(moe_gemm_kernel<FFN_, HID_, false>,
                         cudaFuncAttributeMaxDynamicSharedMemorySize, SMEM_BYTES);

    init_kernel<<<(MAX_SLOTS + 255) / 256, 256>>>();
    router_kernel<<<(T_ * 32 + 255) / 256, 256>>>(x, Wr);
    scan_kernel<<<1, 32>>>();
    scatter_kernel<<<(T_ * 2 + 255) / 256, 256>>>();

    float* w1c; cudaGetSymbolAddress((void**)&w1c, g_W1c);
    float* w2c; cudaGetSymbolAddress((void**)&w2c, g_W2c);
    float* xc;  cudaGetSymbolAddress((void**)&xc,  g_xc);
    {
        int n4 = NE_ * HID_ * FFN_ / 4;
        cvt_tf32_kernel<<<(n4 + 255) / 256, 256>>>((const float4*)W1, (float4*)w1c, n4);
        cvt_tf32_kernel<<<(n4 + 255) / 256, 256>>>((const float4*)W2, (float4*)w2c, n4);
        int nx = T_ * HID_ / 4;
        cvt_tf32_kernel<<<(nx + 255) / 256, 256>>>((const float4*)x, (float4*)xc, nx);
    }

    moe_gemm_kernel<HID_, FFN_, true>
        <<<dim3(ROW_TILES, FFN_ / BN), 256, SMEM_BYTES>>>(xc, w1c, b1);
    moe_gemm_kernel<FFN_, HID_, false>
        <<<dim3(ROW_TILES, HID_ / BN), 256, SMEM_BYTES>>>(xc, w2c, b2);

    combine_kernel<<<(T_ * HID_ / 4 + 255) / 256, 256>>>(out);
}